// round 10
// baseline (speedup 1.0000x reference)
#include <cuda_runtime.h>
#include <cuda_bf16.h>
#include <math.h>
#include <stdint.h>

#define N_NODES 4096
#define NFEAT   1024
#define NHID    128
#define NHEADS  8
#define NCLASS  64
#define ALPHA   0.2f
#define NWORDS  (N_NODES / 32)   // 128 adjacency bitmask words per row
#define NRG     (N_NODES / 16)   // 256 row groups of 16
#define KC1     (NFEAT / 16)     // 64 k-chunks for the two GEMMs (K=1024)
#define AC      (N_NODES / 16)   // 256 k-chunks for the two aggs (K=4096)

typedef uint32_t u32;

// ---------------- scratch (static device memory; no allocation) ----------------
__device__ u32    g_bits [N_NODES * NWORDS];                  // 2 MB
__device__ uint4  g_afx  [NRG * KC1 * 32];                    // x A-frags, 8 MB
__device__ uint2  g_wfrag[NHEADS * KC1 * (NHID / 8) * 32];    // W B-frags, 2 MB
__device__ __nv_bfloat16 g_Whb[NHEADS * N_NODES * NHID];      // Wh bf16, 8 MB
__device__ float  g_f1 [NHEADS * N_NODES];
__device__ float  g_f2 [NHEADS * N_NODES];
__device__ float  g_c1 [NHEADS];
__device__ __align__(16) float2 g_e1[NHEADS * N_NODES];
__device__ __align__(16) float2 g_e2[NHEADS * N_NODES];
__device__ uint2  g_whf  [NHEADS * AC * (NHID / 8) * 32];     // Wh B-frags, 8 MB
__device__ uint4  g_afh  [NRG * KC1 * 32];                    // hcat A-frags, 8 MB
__device__ uint2  g_wofrag[KC1 * (NCLASS / 8) * 32];          // Wo B-frags
__device__ __nv_bfloat16 g_Whob[N_NODES * NCLASS];            // Who bf16
__device__ float  g_g1 [N_NODES];
__device__ float  g_g2 [N_NODES];
__device__ float  g_c2 [1];
__device__ __align__(16) float2 g_e1o[N_NODES];
__device__ __align__(16) float2 g_e2o[N_NODES];
__device__ uint2  g_whof [AC * (NCLASS / 8) * 32];            // Who B-frags
__device__ float  g_obuf [N_NODES * NCLASS];

__device__ __forceinline__ float elu_f(float x) { return x > 0.f ? x : expm1f(x); }

__device__ __forceinline__ u32 pack_bf2(float lo, float hi) {
    __nv_bfloat162 v = __floats2bfloat162_rn(lo, hi);
    return *(u32*)&v;
}

#define MMA_BF16(ac, A0, A1, A2, A3, B0, B1) \
    asm volatile("mma.sync.aligned.m16n8k16.row.col.f32.bf16.bf16.f32 " \
                 "{%0,%1,%2,%3},{%4,%5,%6,%7},{%8,%9},{%0,%1,%2,%3};" \
                 : "+f"((ac)[0]), "+f"((ac)[1]), "+f"((ac)[2]), "+f"((ac)[3]) \
                 : "r"(A0), "r"(A1), "r"(A2), "r"(A3), "r"(B0), "r"(B1))

// ---------------- adjacency -> bitmask ----------------
__global__ void pack_adj_kernel(const int* __restrict__ adj, u32* __restrict__ bits)
{
    const int row = blockIdx.x, wid = threadIdx.x >> 5, lane = threadIdx.x & 31;
    for (int wq = wid; wq < NWORDS; wq += 8) {
        int j = wq * 32 + lane;
        u32 b = __ballot_sync(0xffffffffu, adj[(size_t)row * N_NODES + j] != 0);
        if (lane == 0) bits[row * NWORDS + wq] = b;
    }
}

// ---------------- prep: x fp32 -> bf16 A-fragments ----------------
__global__ void prep_afx_kernel(const float* __restrict__ x, uint4* __restrict__ af)
{
    const int c = blockIdx.x;
    const int w = threadIdx.x >> 5, lane = threadIdx.x & 31;
    const int rg = blockIdx.y * 8 + w;
    const int tg = lane & 3, g = lane >> 2;
    const float* p = x + (size_t)(rg * 16 + g) * NFEAT + c * 16 + tg * 2;
    float2 x0 = *(const float2*)p;
    float2 x1 = *(const float2*)(p + 8 * NFEAT);
    float2 x2 = *(const float2*)(p + 8);
    float2 x3 = *(const float2*)(p + 8 * NFEAT + 8);
    uint4 v;
    v.x = pack_bf2(x0.x, x0.y);
    v.y = pack_bf2(x1.x, x1.y);
    v.z = pack_bf2(x2.x, x2.y);
    v.w = pack_bf2(x3.x, x3.y);
    af[((size_t)rg * KC1 + c) * 32 + lane] = v;
}

// ---------------- prep: fp32 [h][chunks*16][cols] -> bf16 B fragments ----------
__global__ void prep_frag_kernel(const float* __restrict__ src, uint2* __restrict__ dst,
                                 int cols)
{
    const int c = blockIdx.x, h = blockIdx.y, tid = threadIdx.x;
    const int t = tid >> 5, l = tid & 31;
    const int tg = l & 3, g = l >> 2;
    const int NT = cols / 8;
    const int nchunk = gridDim.x;
    const float* p = src + (size_t)h * nchunk * 16 * cols
                   + (size_t)(c * 16 + tg * 2) * cols + t * 8 + g;
    uint2 v;
    v.x = pack_bf2(p[0], p[cols]);
    v.y = pack_bf2(p[8 * cols], p[9 * cols]);
    dst[((size_t)(h * nchunk + c) * NT + t) * 32 + l] = v;
}

// ---------------- prep: bf16 [h][chunks*16][cols] -> B fragments ----------------
__global__ void prep_fragb_kernel(const __nv_bfloat16* __restrict__ src,
                                  uint2* __restrict__ dst, int cols)
{
    const int c = blockIdx.x, h = blockIdx.y, tid = threadIdx.x;
    const int t = tid >> 5, l = tid & 31;
    const int tg = l & 3, g = l >> 2;
    const int NT = cols / 8;
    const int nchunk = gridDim.x;
    const __nv_bfloat16* p = src + (size_t)h * nchunk * 16 * cols
                           + (size_t)(c * 16 + tg * 2) * cols + t * 8 + g;
    uint2 v;
    v.x = (u32)__bfloat16_as_ushort(p[0])        | ((u32)__bfloat16_as_ushort(p[cols])     << 16);
    v.y = (u32)__bfloat16_as_ushort(p[8 * cols]) | ((u32)__bfloat16_as_ushort(p[9 * cols]) << 16);
    dst[((size_t)(h * nchunk + c) * NT + t) * 32 + l] = v;
}

// ---------------- fragment GEMM: Cb[h] = A @ B[h] (bf16 out) + fused dots -------
template<int NT>
__global__ void __launch_bounds__(128)
gemm_frag_kernel(const uint4* __restrict__ afrag, const uint2* __restrict__ bfrag,
                 __nv_bfloat16* __restrict__ Cb, long cHead,
                 const float* __restrict__ v1, const float* __restrict__ v2,
                 float* __restrict__ o1, float* __restrict__ o2)
{
    const int tid = threadIdx.x;
    const int w = tid >> 5, lane = tid & 31;
    const int tg = lane & 3, g = lane >> 2;
    const int h = blockIdx.y;
    const int rg = blockIdx.x * 4 + w;
    const int r0 = rg * 16 + g, r1 = r0 + 8;
    const int ldC = NT * 8;

    const uint4* af = afrag + (size_t)rg * KC1 * 32 + lane;
    const uint2* bf = bfrag + (size_t)h * KC1 * NT * 32 + lane;

    float acc[NT][4];
#pragma unroll
    for (int t = 0; t < NT; t++)
#pragma unroll
        for (int q = 0; q < 4; q++) acc[t][q] = 0.f;

    for (int c = 0; c < KC1; c++) {
        uint4 a = af[(size_t)c * 32];
        const uint2* bp = bf + (size_t)c * NT * 32;
#pragma unroll
        for (int t = 0; t < NT; t++) {
            uint2 b = bp[t * 32];
            MMA_BF16(acc[t], a.x, a.y, a.z, a.w, b.x, b.y);
        }
    }

    // bf16 C
    __nv_bfloat16* c0 = Cb + (size_t)h * cHead + (size_t)r0 * ldC + tg * 2;
    __nv_bfloat16* c1 = Cb + (size_t)h * cHead + (size_t)r1 * ldC + tg * 2;
#pragma unroll
    for (int t = 0; t < NT; t++) {
        *(__nv_bfloat162*)(c0 + t * 8) = __floats2bfloat162_rn(acc[t][0], acc[t][1]);
        *(__nv_bfloat162*)(c1 + t * 8) = __floats2bfloat162_rn(acc[t][2], acc[t][3]);
    }

    // fused dots with v1, v2 (fp32 accumulators)
    const float* w1 = v1 + h * ldC;
    const float* w2 = v2 + h * ldC;
    float s10 = 0.f, s11 = 0.f, s20 = 0.f, s21 = 0.f;
#pragma unroll
    for (int t = 0; t < NT; t++) {
        const int d = t * 8 + tg * 2;
        float u0 = w1[d], u1 = w1[d + 1];
        float q0 = w2[d], q1 = w2[d + 1];
        s10 += acc[t][0] * u0 + acc[t][1] * u1;
        s11 += acc[t][2] * u0 + acc[t][3] * u1;
        s20 += acc[t][0] * q0 + acc[t][1] * q1;
        s21 += acc[t][2] * q0 + acc[t][3] * q1;
    }
#pragma unroll
    for (int o = 1; o <= 2; o <<= 1) {
        s10 += __shfl_xor_sync(0xffffffffu, s10, o);
        s11 += __shfl_xor_sync(0xffffffffu, s11, o);
        s20 += __shfl_xor_sync(0xffffffffu, s20, o);
        s21 += __shfl_xor_sync(0xffffffffu, s21, o);
    }
    if (tg == 0) {
        o1[h * N_NODES + r0] = s10;
        o1[h * N_NODES + r1] = s11;
        o2[h * N_NODES + r0] = s20;
        o2[h * N_NODES + r1] = s21;
    }
}

// ---------------- per-head unmasked max of f2 ----------------
__global__ void headmax_kernel(const float* __restrict__ v, float* __restrict__ c)
{
    __shared__ float red[256];
    const int h = blockIdx.x, tid = threadIdx.x;
    float mx = -INFINITY;
    for (int j = tid; j < N_NODES; j += 256) mx = fmaxf(mx, v[h * N_NODES + j]);
    red[tid] = mx;
    __syncthreads();
    for (int s = 128; s > 0; s >>= 1) {
        if (tid < s) red[tid] = fmaxf(red[tid], red[tid + s]);
        __syncthreads();
    }
    if (tid == 0) c[h] = red[0];
}

// ---------------- factorized exp tables (M_i = lrelu(f1_i + c_h) inline) -------
__global__ void fill_e_kernel(const float* __restrict__ f1, const float* __restrict__ f2,
                              const float* __restrict__ c,
                              float2* __restrict__ e1, float2* __restrict__ e2)
{
    const int idx = blockIdx.x * 256 + threadIdx.x;
    const int h = idx >> 12;
    const float ch = c[h];
    const float s = f1[idx] + ch;
    const float M = fmaxf(s, ALPHA * s);          // >= masked row max, softmax-safe
    const float t = f2[idx] - ch;
    e1[idx] = make_float2(__expf(s - M), __expf(ALPHA * s - M));
    e2[idx] = make_float2(__expf(t), __expf(ALPHA * t));
}

// ---------------- attention apply: P built via max(u+e+, u-e-), 1-term bf16 ----
// AFRAG=true: epilogue writes elu(out/Z) directly as L2 A-fragments.
template<int NT, bool AFRAG>
__global__ void __launch_bounds__(128)
agg_kernel(const u32* __restrict__ bits, const float2* __restrict__ e1,
           const float2* __restrict__ e2, const uint2* __restrict__ bfrag,
           void* __restrict__ outp)
{
    const int tid = threadIdx.x;
    const int w = tid >> 5, lane = tid & 31;
    const int tg = lane & 3, g = lane >> 2;
    const int h = blockIdx.y;
    const int hN = h * N_NODES;
    const int rg = blockIdx.x * 4 + w;
    const int r0 = rg * 16 + g, r1 = r0 + 8;

    const float2 E1a = e1[hN + r0], E1b = e1[hN + r1];
    const float2* e2h = e2 + hN;
    const u32* rowA = bits + (size_t)r0 * NWORDS;
    const u32* rowB = bits + (size_t)r1 * NWORDS;
    const uint2* bf = bfrag + (size_t)h * AC * NT * 32 + lane;

    float acc[NT][4];
#pragma unroll
    for (int t = 0; t < NT; t++)
#pragma unroll
        for (int q = 0; q < 4; q++) acc[t][q] = 0.f;

    float z0 = 0.f, z1 = 0.f;
    u32 wA = 0, wB = 0;

    for (int c = 0; c < AC; c++) {
        if (!(c & 1)) { wA = rowA[c >> 1]; wB = rowB[c >> 1]; }
        const int sh = (c & 1) * 16 + tg * 2;
        const int jA = c * 16 + tg * 2;
        const int jB = jA + 8;
        float4 eA = *(const float4*)(e2h + jA);   // (e+_jA, e-_jA, e+_jA+1, e-_jA+1)
        float4 eB = *(const float4*)(e2h + jB);

        float p00 = ((wA >> sh)       & 1u) ? fmaxf(E1a.x * eA.x, E1a.y * eA.y) : 0.f;
        float p01 = ((wA >> (sh + 1)) & 1u) ? fmaxf(E1a.x * eA.z, E1a.y * eA.w) : 0.f;
        float p02 = ((wA >> (sh + 8)) & 1u) ? fmaxf(E1a.x * eB.x, E1a.y * eB.y) : 0.f;
        float p03 = ((wA >> (sh + 9)) & 1u) ? fmaxf(E1a.x * eB.z, E1a.y * eB.w) : 0.f;
        float p10 = ((wB >> sh)       & 1u) ? fmaxf(E1b.x * eA.x, E1b.y * eA.y) : 0.f;
        float p11 = ((wB >> (sh + 1)) & 1u) ? fmaxf(E1b.x * eA.z, E1b.y * eA.w) : 0.f;
        float p12 = ((wB >> (sh + 8)) & 1u) ? fmaxf(E1b.x * eB.x, E1b.y * eB.y) : 0.f;
        float p13 = ((wB >> (sh + 9)) & 1u) ? fmaxf(E1b.x * eB.z, E1b.y * eB.w) : 0.f;

        z0 += (p00 + p01) + (p02 + p03);
        z1 += (p10 + p11) + (p12 + p13);

        u32 a0 = pack_bf2(p00, p01);
        u32 a1 = pack_bf2(p10, p11);
        u32 a2 = pack_bf2(p02, p03);
        u32 a3 = pack_bf2(p12, p13);

        const uint2* bp = bf + (size_t)c * NT * 32;
#pragma unroll
        for (int t = 0; t < NT; t++) {
            uint2 b = bp[t * 32];
            MMA_BF16(acc[t], a0, a1, a2, a3, b.x, b.y);
        }
    }

    z0 += __shfl_xor_sync(0xffffffffu, z0, 1);
    z0 += __shfl_xor_sync(0xffffffffu, z0, 2);
    z1 += __shfl_xor_sync(0xffffffffu, z1, 1);
    z1 += __shfl_xor_sync(0xffffffffu, z1, 2);
    const float iz0 = 1.f / z0;
    const float iz1 = 1.f / z1;

    if (AFRAG) {
        // write elu(out/Z) as A-fragments of the concatenated feature matrix
        uint4* af = (uint4*)outp;
#pragma unroll
        for (int ct = 0; ct < NT / 2; ct++) {
            const int t0 = 2 * ct, t1 = 2 * ct + 1;
            uint4 v;
            v.x = pack_bf2(elu_f(acc[t0][0] * iz0), elu_f(acc[t0][1] * iz0));
            v.y = pack_bf2(elu_f(acc[t0][2] * iz1), elu_f(acc[t0][3] * iz1));
            v.z = pack_bf2(elu_f(acc[t1][0] * iz0), elu_f(acc[t1][1] * iz0));
            v.w = pack_bf2(elu_f(acc[t1][2] * iz1), elu_f(acc[t1][3] * iz1));
            af[((size_t)rg * KC1 + h * (NT / 2) + ct) * 32 + lane] = v;
        }
    } else {
        float* out = (float*)outp;
        float* row0 = out + (size_t)r0 * (NT * 8) + tg * 2;
        float* row1 = out + (size_t)r1 * (NT * 8) + tg * 2;
#pragma unroll
        for (int t = 0; t < NT; t++) {
            *(float2*)(row0 + t * 8) = make_float2(elu_f(acc[t][0] * iz0),
                                                   elu_f(acc[t][1] * iz0));
            *(float2*)(row1 + t * 8) = make_float2(elu_f(acc[t][2] * iz1),
                                                   elu_f(acc[t][3] * iz1));
        }
    }
}

// ---------------- final log_softmax over 64 classes ----------------
__global__ void lsm_kernel(const float* __restrict__ in, float* __restrict__ out)
{
    int warp = (blockIdx.x * blockDim.x + threadIdx.x) >> 5;
    int lane = threadIdx.x & 31;
    if (warp >= N_NODES) return;
    const float* row = in + (long)warp * NCLASS;
    float v0 = row[lane];
    float v1 = row[lane + 32];
    float m = fmaxf(v0, v1);
#pragma unroll
    for (int o = 16; o > 0; o >>= 1) m = fmaxf(m, __shfl_xor_sync(0xffffffffu, m, o));
    float s = expf(v0 - m) + expf(v1 - m);
#pragma unroll
    for (int o = 16; o > 0; o >>= 1) s += __shfl_xor_sync(0xffffffffu, s, o);
    float ls = m + logf(s);
    out[(long)warp * NCLASS + lane]      = v0 - ls;
    out[(long)warp * NCLASS + lane + 32] = v1 - ls;
}

// ---------------- launch ----------------
extern "C" void kernel_launch(void* const* d_in, const int* in_sizes, int n_in,
                              void* d_out, int out_size)
{
    const float* x   = (const float*)d_in[0];
    const int*   adj = (const int*)  d_in[1];
    const float* W   = (const float*)d_in[2];
    const float* a1  = (const float*)d_in[3];
    const float* a2  = (const float*)d_in[4];
    const float* Wo  = (const float*)d_in[5];
    const float* ao1 = (const float*)d_in[6];
    const float* ao2 = (const float*)d_in[7];
    float* out = (float*)d_out;

    u32* bits;
    uint4 *afx, *afh;
    uint2 *wfrag, *wofrag, *whf, *whof;
    __nv_bfloat16 *Whb, *Whob;
    float *f1, *f2, *c1, *g1, *g2, *c2, *obuf;
    float2 *e1, *e2, *e1o, *e2o;
    cudaGetSymbolAddress((void**)&bits,   g_bits);
    cudaGetSymbolAddress((void**)&afx,    g_afx);
    cudaGetSymbolAddress((void**)&wfrag,  g_wfrag);
    cudaGetSymbolAddress((void**)&Whb,    g_Whb);
    cudaGetSymbolAddress((void**)&f1,     g_f1);
    cudaGetSymbolAddress((void**)&f2,     g_f2);
    cudaGetSymbolAddress((void**)&c1,     g_c1);
    cudaGetSymbolAddress((void**)&e1,     g_e1);
    cudaGetSymbolAddress((void**)&e2,     g_e2);
    cudaGetSymbolAddress((void**)&whf,    g_whf);
    cudaGetSymbolAddress((void**)&afh,    g_afh);
    cudaGetSymbolAddress((void**)&wofrag, g_wofrag);
    cudaGetSymbolAddress((void**)&Whob,   g_Whob);
    cudaGetSymbolAddress((void**)&g1,     g_g1);
    cudaGetSymbolAddress((void**)&g2,     g_g2);
    cudaGetSymbolAddress((void**)&c2,     g_c2);
    cudaGetSymbolAddress((void**)&e1o,    g_e1o);
    cudaGetSymbolAddress((void**)&e2o,    g_e2o);
    cudaGetSymbolAddress((void**)&whof,   g_whof);
    cudaGetSymbolAddress((void**)&obuf,   g_obuf);

    // preprocessing
    pack_adj_kernel<<<N_NODES, 256>>>(adj, bits);
    prep_afx_kernel<<<dim3(KC1, NRG / 8), 256>>>(x, afx);
    prep_frag_kernel<<<dim3(KC1, NHEADS), 512>>>(W, wfrag, NHID);

    // ---- layer 1 ----
    gemm_frag_kernel<16><<<dim3(NRG / 4, NHEADS), 128>>>(
        afx, wfrag, Whb, (long)N_NODES * NHID, a1, a2, f1, f2);
    headmax_kernel<<<NHEADS, 256>>>(f2, c1);
    fill_e_kernel<<<(NHEADS * N_NODES) / 256, 256>>>(f1, f2, c1, e1, e2);
    prep_fragb_kernel<<<dim3(AC, NHEADS), 512>>>(Whb, whf, NHID);
    agg_kernel<16, true><<<dim3(NRG / 4, NHEADS), 128>>>(bits, e1, e2, whf, afh);

    // ---- layer 2 ----
    prep_frag_kernel<<<dim3(KC1, 1), 256>>>(Wo, wofrag, NCLASS);
    gemm_frag_kernel<8><<<dim3(NRG / 4, 1), 128>>>(
        afh, wofrag, Whob, 0, ao1, ao2, g1, g2);
    headmax_kernel<<<1, 256>>>(g2, c2);
    fill_e_kernel<<<N_NODES / 256, 256>>>(g1, g2, c2, e1o, e2o);
    prep_fragb_kernel<<<dim3(AC, 1), 256>>>(Whob, whof, NCLASS);
    agg_kernel<8, false><<<dim3(NRG / 4, 1), 128>>>(bits, e1o, e2o, whof, obuf);

    lsm_kernel<<<N_NODES / 8, 256>>>(obuf, out);
}

// round 11
// speedup vs baseline: 2.5498x; 2.5498x over previous
#include <cuda_runtime.h>
#include <cuda_bf16.h>
#include <math.h>
#include <stdint.h>

#define N_NODES 4096
#define NFEAT   1024
#define NHID    128
#define NHEADS  8
#define NCLASS  64
#define ALPHA   0.2f
#define NWORDS  (N_NODES / 32)   // 128 adjacency bitmask words per row
#define NRG     (N_NODES / 16)   // 256 row groups of 16
#define KC1     (NFEAT / 16)     // 64 k-chunks for the two GEMMs (K=1024)
#define AC      (N_NODES / 16)   // 256 k-chunks for the two aggs (K=4096)

typedef uint32_t u32;

// ---------------- scratch (static device memory; no allocation) ----------------
__device__ u32    g_bits [N_NODES * NWORDS];                  // 2 MB
__device__ uint4  g_afx  [NRG * KC1 * 32];                    // x A-frags, 8 MB
__device__ uint2  g_wfrag[NHEADS * KC1 * (NHID / 8) * 32];    // W B-frags, 2 MB
__device__ __nv_bfloat16 g_Whb[NHEADS * N_NODES * NHID];      // Wh bf16, 8 MB
__device__ float  g_f1 [NHEADS * N_NODES];
__device__ float  g_f2 [NHEADS * N_NODES];
__device__ float  g_c1 [NHEADS];
__device__ __align__(16) float2 g_e1[NHEADS * N_NODES];
__device__ __align__(16) float2 g_e2[NHEADS * N_NODES];
__device__ uint2  g_whf  [NHEADS * AC * (NHID / 8) * 32];     // Wh B-frags, 8 MB
__device__ uint4  g_afh  [NRG * KC1 * 32];                    // hcat A-frags, 8 MB
__device__ uint2  g_wofrag[KC1 * (NCLASS / 8) * 32];          // Wo B-frags
__device__ __nv_bfloat16 g_Whob[N_NODES * NCLASS];            // Who bf16
__device__ float  g_g1 [N_NODES];
__device__ float  g_g2 [N_NODES];
__device__ float  g_c2 [1];
__device__ __align__(16) float2 g_e1o[N_NODES];
__device__ __align__(16) float2 g_e2o[N_NODES];
__device__ uint2  g_whof [AC * (NCLASS / 8) * 32];            // Who B-frags
__device__ float  g_obuf [N_NODES * NCLASS];

__device__ __forceinline__ float elu_f(float x) { return x > 0.f ? x : expm1f(x); }

__device__ __forceinline__ u32 pack_bf2(float lo, float hi) {
    __nv_bfloat162 v = __floats2bfloat162_rn(lo, hi);
    return *(u32*)&v;
}

#define MMA_BF16(ac, A0, A1, A2, A3, B0, B1) \
    asm volatile("mma.sync.aligned.m16n8k16.row.col.f32.bf16.bf16.f32 " \
                 "{%0,%1,%2,%3},{%4,%5,%6,%7},{%8,%9},{%0,%1,%2,%3};" \
                 : "+f"((ac)[0]), "+f"((ac)[1]), "+f"((ac)[2]), "+f"((ac)[3]) \
                 : "r"(A0), "r"(A1), "r"(A2), "r"(A3), "r"(B0), "r"(B1))

__device__ __forceinline__ void cp_async16(void* smem_dst, const void* gmem_src) {
    u32 s = (u32)__cvta_generic_to_shared(smem_dst);
    asm volatile("cp.async.cg.shared.global [%0], [%1], 16;" :: "r"(s), "l"(gmem_src));
}
#define CP_COMMIT()  asm volatile("cp.async.commit_group;" ::: "memory")
#define CP_WAIT(n)   asm volatile("cp.async.wait_group %0;" :: "n"(n) : "memory")

// stage BYTES of B-fragments into smem (256 threads, 16B each)
template<int BYTES>
__device__ __forceinline__ void stage_chunk(void* dst, const void* src, int tid) {
#pragma unroll
    for (int off = tid * 16; off < BYTES; off += 256 * 16)
        cp_async16((char*)dst + off, (const char*)src + off);
}

// ---------------- adjacency -> bitmask ----------------
__global__ void pack_adj_kernel(const int* __restrict__ adj, u32* __restrict__ bits)
{
    const int row = blockIdx.x, wid = threadIdx.x >> 5, lane = threadIdx.x & 31;
    for (int wq = wid; wq < NWORDS; wq += 8) {
        int j = wq * 32 + lane;
        u32 b = __ballot_sync(0xffffffffu, adj[(size_t)row * N_NODES + j] != 0);
        if (lane == 0) bits[row * NWORDS + wq] = b;
    }
}

// ---------------- prep: x fp32 -> bf16 A-fragments ----------------
__global__ void prep_afx_kernel(const float* __restrict__ x, uint4* __restrict__ af)
{
    const int c = blockIdx.x;
    const int w = threadIdx.x >> 5, lane = threadIdx.x & 31;
    const int rg = blockIdx.y * 8 + w;
    const int tg = lane & 3, g = lane >> 2;
    const float* p = x + (size_t)(rg * 16 + g) * NFEAT + c * 16 + tg * 2;
    float2 x0 = *(const float2*)p;
    float2 x1 = *(const float2*)(p + 8 * NFEAT);
    float2 x2 = *(const float2*)(p + 8);
    float2 x3 = *(const float2*)(p + 8 * NFEAT + 8);
    uint4 v;
    v.x = pack_bf2(x0.x, x0.y);
    v.y = pack_bf2(x1.x, x1.y);
    v.z = pack_bf2(x2.x, x2.y);
    v.w = pack_bf2(x3.x, x3.y);
    af[((size_t)rg * KC1 + c) * 32 + lane] = v;
}

// ---------------- prep: fp32 [h][chunks*16][cols] -> bf16 B fragments ----------
__global__ void prep_frag_kernel(const float* __restrict__ src, uint2* __restrict__ dst,
                                 int cols)
{
    const int c = blockIdx.x, h = blockIdx.y, tid = threadIdx.x;
    const int t = tid >> 5, l = tid & 31;
    const int tg = l & 3, g = l >> 2;
    const int NT = cols / 8;
    const int nchunk = gridDim.x;
    const float* p = src + (size_t)h * nchunk * 16 * cols
                   + (size_t)(c * 16 + tg * 2) * cols + t * 8 + g;
    uint2 v;
    v.x = pack_bf2(p[0], p[cols]);
    v.y = pack_bf2(p[8 * cols], p[9 * cols]);
    dst[((size_t)(h * nchunk + c) * NT + t) * 32 + l] = v;
}

// ---------------- prep: bf16 [h][chunks*16][cols] -> B fragments ----------------
__global__ void prep_fragb_kernel(const __nv_bfloat16* __restrict__ src,
                                  uint2* __restrict__ dst, int cols)
{
    const int c = blockIdx.x, h = blockIdx.y, tid = threadIdx.x;
    const int t = tid >> 5, l = tid & 31;
    const int tg = l & 3, g = l >> 2;
    const int NT = cols / 8;
    const int nchunk = gridDim.x;
    const __nv_bfloat16* p = src + (size_t)h * nchunk * 16 * cols
                           + (size_t)(c * 16 + tg * 2) * cols + t * 8 + g;
    uint2 v;
    v.x = (u32)__bfloat16_as_ushort(p[0])        | ((u32)__bfloat16_as_ushort(p[cols])     << 16);
    v.y = (u32)__bfloat16_as_ushort(p[8 * cols]) | ((u32)__bfloat16_as_ushort(p[9 * cols]) << 16);
    dst[((size_t)(h * nchunk + c) * NT + t) * 32 + l] = v;
}

// ---------------- fragment GEMM (smem-staged B): Cb[h] = A @ B[h] + fused dots --
// 256 threads, 8 warps; warp w -> row group rg = blockIdx.x*8 + w.
template<int NT>
__global__ void __launch_bounds__(256)
gemm_frag_kernel(const uint4* __restrict__ afrag, const uint2* __restrict__ bfrag,
                 __nv_bfloat16* __restrict__ Cb, long cHead,
                 const float* __restrict__ v1, const float* __restrict__ v2,
                 float* __restrict__ o1, float* __restrict__ o2)
{
    __shared__ __align__(16) uint2 sB[2][NT * 32];
    const int tid = threadIdx.x;
    const int w = tid >> 5, lane = tid & 31;
    const int tg = lane & 3, g = lane >> 2;
    const int h = blockIdx.y;
    const int rg = blockIdx.x * 8 + w;
    const int r0 = rg * 16 + g, r1 = r0 + 8;
    const int ldC = NT * 8;

    const uint4* af = afrag + (size_t)rg * KC1 * 32 + lane;
    const uint2* bf = bfrag + (size_t)h * KC1 * NT * 32;

    float acc[NT][4];
#pragma unroll
    for (int t = 0; t < NT; t++)
#pragma unroll
        for (int q = 0; q < 4; q++) acc[t][q] = 0.f;

    stage_chunk<NT * 256>(sB[0], bf, tid);
    CP_COMMIT();
    uint4 a_cur = af[0];

    for (int c = 0; c < KC1; c++) {
        uint4 a_nxt;
        if (c + 1 < KC1) {
            a_nxt = af[(size_t)(c + 1) * 32];
            stage_chunk<NT * 256>(sB[(c + 1) & 1], bf + (size_t)(c + 1) * NT * 32, tid);
            CP_COMMIT();
            CP_WAIT(1);
        } else {
            CP_WAIT(0);
        }
        __syncthreads();
        const uint2* bp = sB[c & 1] + lane;
#pragma unroll
        for (int t = 0; t < NT; t++) {
            uint2 b = bp[t * 32];
            MMA_BF16(acc[t], a_cur.x, a_cur.y, a_cur.z, a_cur.w, b.x, b.y);
        }
        __syncthreads();
        if (c + 1 < KC1) a_cur = a_nxt;
    }

    // bf16 C
    __nv_bfloat16* c0 = Cb + (size_t)h * cHead + (size_t)r0 * ldC + tg * 2;
    __nv_bfloat16* c1 = Cb + (size_t)h * cHead + (size_t)r1 * ldC + tg * 2;
#pragma unroll
    for (int t = 0; t < NT; t++) {
        *(__nv_bfloat162*)(c0 + t * 8) = __floats2bfloat162_rn(acc[t][0], acc[t][1]);
        *(__nv_bfloat162*)(c1 + t * 8) = __floats2bfloat162_rn(acc[t][2], acc[t][3]);
    }

    // fused dots with v1, v2
    const float* w1 = v1 + h * ldC;
    const float* w2 = v2 + h * ldC;
    float s10 = 0.f, s11 = 0.f, s20 = 0.f, s21 = 0.f;
#pragma unroll
    for (int t = 0; t < NT; t++) {
        const int d = t * 8 + tg * 2;
        float u0 = w1[d], u1 = w1[d + 1];
        float q0 = w2[d], q1 = w2[d + 1];
        s10 += acc[t][0] * u0 + acc[t][1] * u1;
        s11 += acc[t][2] * u0 + acc[t][3] * u1;
        s20 += acc[t][0] * q0 + acc[t][1] * q1;
        s21 += acc[t][2] * q0 + acc[t][3] * q1;
    }
#pragma unroll
    for (int o = 1; o <= 2; o <<= 1) {
        s10 += __shfl_xor_sync(0xffffffffu, s10, o);
        s11 += __shfl_xor_sync(0xffffffffu, s11, o);
        s20 += __shfl_xor_sync(0xffffffffu, s20, o);
        s21 += __shfl_xor_sync(0xffffffffu, s21, o);
    }
    if (tg == 0) {
        o1[h * N_NODES + r0] = s10;
        o1[h * N_NODES + r1] = s11;
        o2[h * N_NODES + r0] = s20;
        o2[h * N_NODES + r1] = s21;
    }
}

// ---------------- per-head unmasked max of f2 ----------------
__global__ void headmax_kernel(const float* __restrict__ v, float* __restrict__ c)
{
    __shared__ float red[256];
    const int h = blockIdx.x, tid = threadIdx.x;
    float mx = -INFINITY;
    for (int j = tid; j < N_NODES; j += 256) mx = fmaxf(mx, v[h * N_NODES + j]);
    red[tid] = mx;
    __syncthreads();
    for (int s = 128; s > 0; s >>= 1) {
        if (tid < s) red[tid] = fmaxf(red[tid], red[tid + s]);
        __syncthreads();
    }
    if (tid == 0) c[h] = red[0];
}

// ---------------- factorized exp tables (M_i = lrelu(f1_i + c_h) inline) -------
__global__ void fill_e_kernel(const float* __restrict__ f1, const float* __restrict__ f2,
                              const float* __restrict__ c,
                              float2* __restrict__ e1, float2* __restrict__ e2)
{
    const int idx = blockIdx.x * 256 + threadIdx.x;
    const int h = idx >> 12;
    const float ch = c[h];
    const float s = f1[idx] + ch;
    const float M = fmaxf(s, ALPHA * s);          // >= masked row max, softmax-safe
    const float t = f2[idx] - ch;
    e1[idx] = make_float2(__expf(s - M), __expf(ALPHA * s - M));
    e2[idx] = make_float2(__expf(t), __expf(ALPHA * t));
}

// ---------------- attention apply (smem-staged B, factorized P) ----------------
// 256 threads, 8 warps; warp w -> row group rg = blockIdx.x*8 + w.
template<int NT, bool AFRAG>
__global__ void __launch_bounds__(256)
agg_kernel(const u32* __restrict__ bits, const float2* __restrict__ e1,
           const float2* __restrict__ e2, const uint2* __restrict__ bfrag,
           void* __restrict__ outp)
{
    __shared__ __align__(16) uint2 sB[2][NT * 32];
    const int tid = threadIdx.x;
    const int w = tid >> 5, lane = tid & 31;
    const int tg = lane & 3, g = lane >> 2;
    const int h = blockIdx.y;
    const int hN = h * N_NODES;
    const int rg = blockIdx.x * 8 + w;
    const int r0 = rg * 16 + g, r1 = r0 + 8;

    const float2 E1a = e1[hN + r0], E1b = e1[hN + r1];
    const float2* e2h = e2 + hN;
    const u32* rowA = bits + (size_t)r0 * NWORDS;
    const u32* rowB = bits + (size_t)r1 * NWORDS;
    const uint2* bf = bfrag + (size_t)h * AC * NT * 32;

    float acc[NT][4];
#pragma unroll
    for (int t = 0; t < NT; t++)
#pragma unroll
        for (int q = 0; q < 4; q++) acc[t][q] = 0.f;

    float z0 = 0.f, z1 = 0.f;

    stage_chunk<NT * 256>(sB[0], bf, tid);
    CP_COMMIT();

    u32 curA = rowA[0], curB = rowB[0], nxtA = 0, nxtB = 0;
    u32 wA = 0, wB = 0;

    for (int c = 0; c < AC; c++) {
        if (!(c & 1)) {
            wA = curA; wB = curB;
            int nw = (c >> 1) + 1;
            if (nw < NWORDS) { nxtA = rowA[nw]; nxtB = rowB[nw]; }
        }
        if (c + 1 < AC) {
            stage_chunk<NT * 256>(sB[(c + 1) & 1], bf + (size_t)(c + 1) * NT * 32, tid);
            CP_COMMIT();
            CP_WAIT(1);
        } else {
            CP_WAIT(0);
        }

        const int sh = (c & 1) * 16 + tg * 2;
        const int jA = c * 16 + tg * 2;
        const int jB = jA + 8;
        float4 eA = *(const float4*)(e2h + jA);   // (e+_jA, e-_jA, e+_jA+1, e-_jA+1)
        float4 eB = *(const float4*)(e2h + jB);

        float p00 = ((wA >> sh)       & 1u) ? fmaxf(E1a.x * eA.x, E1a.y * eA.y) : 0.f;
        float p01 = ((wA >> (sh + 1)) & 1u) ? fmaxf(E1a.x * eA.z, E1a.y * eA.w) : 0.f;
        float p02 = ((wA >> (sh + 8)) & 1u) ? fmaxf(E1a.x * eB.x, E1a.y * eB.y) : 0.f;
        float p03 = ((wA >> (sh + 9)) & 1u) ? fmaxf(E1a.x * eB.z, E1a.y * eB.w) : 0.f;
        float p10 = ((wB >> sh)       & 1u) ? fmaxf(E1b.x * eA.x, E1b.y * eA.y) : 0.f;
        float p11 = ((wB >> (sh + 1)) & 1u) ? fmaxf(E1b.x * eA.z, E1b.y * eA.w) : 0.f;
        float p12 = ((wB >> (sh + 8)) & 1u) ? fmaxf(E1b.x * eB.x, E1b.y * eB.y) : 0.f;
        float p13 = ((wB >> (sh + 9)) & 1u) ? fmaxf(E1b.x * eB.z, E1b.y * eB.w) : 0.f;

        z0 += (p00 + p01) + (p02 + p03);
        z1 += (p10 + p11) + (p12 + p13);

        u32 a0 = pack_bf2(p00, p01);
        u32 a1 = pack_bf2(p10, p11);
        u32 a2 = pack_bf2(p02, p03);
        u32 a3 = pack_bf2(p12, p13);

        __syncthreads();
        const uint2* bp = sB[c & 1] + lane;
#pragma unroll
        for (int t = 0; t < NT; t++) {
            uint2 b = bp[t * 32];
            MMA_BF16(acc[t], a0, a1, a2, a3, b.x, b.y);
        }
        __syncthreads();
        if (c & 1) { curA = nxtA; curB = nxtB; }
    }

    z0 += __shfl_xor_sync(0xffffffffu, z0, 1);
    z0 += __shfl_xor_sync(0xffffffffu, z0, 2);
    z1 += __shfl_xor_sync(0xffffffffu, z1, 1);
    z1 += __shfl_xor_sync(0xffffffffu, z1, 2);
    const float iz0 = 1.f / z0;
    const float iz1 = 1.f / z1;

    if (AFRAG) {
        // write elu(out/Z) as A-fragments of the concatenated feature matrix
        uint4* af = (uint4*)outp;
#pragma unroll
        for (int ct = 0; ct < NT / 2; ct++) {
            const int t0 = 2 * ct, t1 = 2 * ct + 1;
            uint4 v;
            v.x = pack_bf2(elu_f(acc[t0][0] * iz0), elu_f(acc[t0][1] * iz0));
            v.y = pack_bf2(elu_f(acc[t0][2] * iz1), elu_f(acc[t0][3] * iz1));
            v.z = pack_bf2(elu_f(acc[t1][0] * iz0), elu_f(acc[t1][1] * iz0));
            v.w = pack_bf2(elu_f(acc[t1][2] * iz1), elu_f(acc[t1][3] * iz1));
            af[((size_t)rg * KC1 + h * (NT / 2) + ct) * 32 + lane] = v;
        }
    } else {
        float* out = (float*)outp;
        float* row0 = out + (size_t)r0 * (NT * 8) + tg * 2;
        float* row1 = out + (size_t)r1 * (NT * 8) + tg * 2;
#pragma unroll
        for (int t = 0; t < NT; t++) {
            *(float2*)(row0 + t * 8) = make_float2(elu_f(acc[t][0] * iz0),
                                                   elu_f(acc[t][1] * iz0));
            *(float2*)(row1 + t * 8) = make_float2(elu_f(acc[t][2] * iz1),
                                                   elu_f(acc[t][3] * iz1));
        }
    }
}

// ---------------- final log_softmax over 64 classes ----------------
__global__ void lsm_kernel(const float* __restrict__ in, float* __restrict__ out)
{
    int warp = (blockIdx.x * blockDim.x + threadIdx.x) >> 5;
    int lane = threadIdx.x & 31;
    if (warp >= N_NODES) return;
    const float* row = in + (long)warp * NCLASS;
    float v0 = row[lane];
    float v1 = row[lane + 32];
    float m = fmaxf(v0, v1);
#pragma unroll
    for (int o = 16; o > 0; o >>= 1) m = fmaxf(m, __shfl_xor_sync(0xffffffffu, m, o));
    float s = expf(v0 - m) + expf(v1 - m);
#pragma unroll
    for (int o = 16; o > 0; o >>= 1) s += __shfl_xor_sync(0xffffffffu, s, o);
    float ls = m + logf(s);
    out[(long)warp * NCLASS + lane]      = v0 - ls;
    out[(long)warp * NCLASS + lane + 32] = v1 - ls;
}

// ---------------- launch ----------------
extern "C" void kernel_launch(void* const* d_in, const int* in_sizes, int n_in,
                              void* d_out, int out_size)
{
    const float* x   = (const float*)d_in[0];
    const int*   adj = (const int*)  d_in[1];
    const float* W   = (const float*)d_in[2];
    const float* a1  = (const float*)d_in[3];
    const float* a2  = (const float*)d_in[4];
    const float* Wo  = (const float*)d_in[5];
    const float* ao1 = (const float*)d_in[6];
    const float* ao2 = (const float*)d_in[7];
    float* out = (float*)d_out;

    u32* bits;
    uint4 *afx, *afh;
    uint2 *wfrag, *wofrag, *whf, *whof;
    __nv_bfloat16 *Whb, *Whob;
    float *f1, *f2, *c1, *g1, *g2, *c2, *obuf;
    float2 *e1, *e2, *e1o, *e2o;
    cudaGetSymbolAddress((void**)&bits,   g_bits);
    cudaGetSymbolAddress((void**)&afx,    g_afx);
    cudaGetSymbolAddress((void**)&wfrag,  g_wfrag);
    cudaGetSymbolAddress((void**)&Whb,    g_Whb);
    cudaGetSymbolAddress((void**)&f1,     g_f1);
    cudaGetSymbolAddress((void**)&f2,     g_f2);
    cudaGetSymbolAddress((void**)&c1,     g_c1);
    cudaGetSymbolAddress((void**)&e1,     g_e1);
    cudaGetSymbolAddress((void**)&e2,     g_e2);
    cudaGetSymbolAddress((void**)&whf,    g_whf);
    cudaGetSymbolAddress((void**)&afh,    g_afh);
    cudaGetSymbolAddress((void**)&wofrag, g_wofrag);
    cudaGetSymbolAddress((void**)&Whob,   g_Whob);
    cudaGetSymbolAddress((void**)&g1,     g_g1);
    cudaGetSymbolAddress((void**)&g2,     g_g2);
    cudaGetSymbolAddress((void**)&c2,     g_c2);
    cudaGetSymbolAddress((void**)&e1o,    g_e1o);
    cudaGetSymbolAddress((void**)&e2o,    g_e2o);
    cudaGetSymbolAddress((void**)&whof,   g_whof);
    cudaGetSymbolAddress((void**)&obuf,   g_obuf);

    // preprocessing
    pack_adj_kernel<<<N_NODES, 256>>>(adj, bits);
    prep_afx_kernel<<<dim3(KC1, NRG / 8), 256>>>(x, afx);
    prep_frag_kernel<<<dim3(KC1, NHEADS), 512>>>(W, wfrag, NHID);

    // ---- layer 1 ----
    gemm_frag_kernel<16><<<dim3(NRG / 8, NHEADS), 256>>>(
        afx, wfrag, Whb, (long)N_NODES * NHID, a1, a2, f1, f2);
    headmax_kernel<<<NHEADS, 256>>>(f2, c1);
    fill_e_kernel<<<(NHEADS * N_NODES) / 256, 256>>>(f1, f2, c1, e1, e2);
    prep_fragb_kernel<<<dim3(AC, NHEADS), 512>>>(Whb, whf, NHID);
    agg_kernel<16, true><<<dim3(NRG / 8, NHEADS), 256>>>(bits, e1, e2, whf, afh);

    // ---- layer 2 ----
    prep_frag_kernel<<<dim3(KC1, 1), 256>>>(Wo, wofrag, NCLASS);
    gemm_frag_kernel<8><<<dim3(NRG / 8, 1), 256>>>(
        afh, wofrag, Whob, 0, ao1, ao2, g1, g2);
    headmax_kernel<<<1, 256>>>(g2, c2);
    fill_e_kernel<<<N_NODES / 256, 256>>>(g1, g2, c2, e1o, e2o);
    prep_fragb_kernel<<<dim3(AC, 1), 256>>>(Whob, whof, NCLASS);
    agg_kernel<8, false><<<dim3(NRG / 8, 1), 256>>>(bits, e1o, e2o, whof, obuf);

    lsm_kernel<<<N_NODES / 8, 256>>>(obuf, out);
}

// round 13
// speedup vs baseline: 3.4889x; 1.3683x over previous
#include <cuda_runtime.h>
#include <cuda_bf16.h>
#include <math.h>
#include <stdint.h>

#define N_NODES 4096
#define NFEAT   1024
#define NHID    128
#define NHEADS  8
#define NCLASS  64
#define ALPHA   0.2f
#define NWORDS  (N_NODES / 32)   // 128 adjacency bitmask words per row
#define NRG     (N_NODES / 16)   // 256 row groups of 16
#define KC1     (NFEAT / 16)     // 64 k-chunks for the two GEMMs (K=1024)
#define AC      (N_NODES / 16)   // 256 k-chunks for the two aggs (K=4096)
#define GRP     4                // k-chunks per staged group

typedef uint32_t u32;

// ---------------- scratch (static device memory; no allocation) ----------------
__device__ u32    g_bits [N_NODES * NWORDS];                  // 2 MB
__device__ uint4  g_afx  [NRG * KC1 * 32];                    // x A-frags, 8 MB
__device__ uint2  g_wfrag[NHEADS * KC1 * (NHID / 8) * 32];    // W B-frags, 2 MB
__device__ float  g_f1 [NHEADS * N_NODES];
__device__ float  g_f2 [NHEADS * N_NODES];
__device__ float  g_c1 [NHEADS];
__device__ __align__(16) float2 g_e1[NHEADS * N_NODES];
__device__ __align__(16) float2 g_e2[NHEADS * N_NODES];
__device__ uint2  g_whf  [NHEADS * AC * (NHID / 8) * 32];     // Wh B-frags, 8 MB
__device__ uint4  g_afh  [NRG * KC1 * 32];                    // hcat A-frags, 8 MB
__device__ uint2  g_wofrag[KC1 * (NCLASS / 8) * 32];          // Wo B-frags
__device__ float  g_g1 [N_NODES];
__device__ float  g_g2 [N_NODES];
__device__ float  g_c2 [1];
__device__ __align__(16) float2 g_e1o[N_NODES];
__device__ __align__(16) float2 g_e2o[N_NODES];
__device__ uint2  g_whof [AC * (NCLASS / 8) * 32];            // Who B-frags
__device__ float  g_obuf [N_NODES * NCLASS];

__device__ __forceinline__ float elu_f(float x) { return x > 0.f ? x : expm1f(x); }

__device__ __forceinline__ u32 pack_bf2(float lo, float hi) {
    __nv_bfloat162 v = __floats2bfloat162_rn(lo, hi);
    return *(u32*)&v;
}

#define MMA_BF16(ac, A0, A1, A2, A3, B0, B1) \
    asm volatile("mma.sync.aligned.m16n8k16.row.col.f32.bf16.bf16.f32 " \
                 "{%0,%1,%2,%3},{%4,%5,%6,%7},{%8,%9},{%0,%1,%2,%3};" \
                 : "+f"((ac)[0]), "+f"((ac)[1]), "+f"((ac)[2]), "+f"((ac)[3]) \
                 : "r"(A0), "r"(A1), "r"(A2), "r"(A3), "r"(B0), "r"(B1))

__device__ __forceinline__ void cp_async16(void* smem_dst, const void* gmem_src) {
    u32 s = (u32)__cvta_generic_to_shared(smem_dst);
    asm volatile("cp.async.cg.shared.global [%0], [%1], 16;" :: "r"(s), "l"(gmem_src));
}
#define CP_COMMIT()  asm volatile("cp.async.commit_group;" ::: "memory")
#define CP_WAIT(n)   asm volatile("cp.async.wait_group %0;" :: "n"(n) : "memory")

// stage BYTES into smem (256 threads, 16B each)
template<int BYTES>
__device__ __forceinline__ void stage_chunk(void* dst, const void* src, int tid) {
#pragma unroll
    for (int off = tid * 16; off < BYTES; off += 256 * 16)
        cp_async16((char*)dst + off, (const char*)src + off);
}

// ---------------- adjacency -> bitmask ----------------
__global__ void pack_adj_kernel(const int* __restrict__ adj, u32* __restrict__ bits)
{
    const int row = blockIdx.x, wid = threadIdx.x >> 5, lane = threadIdx.x & 31;
    for (int wq = wid; wq < NWORDS; wq += 8) {
        int j = wq * 32 + lane;
        u32 b = __ballot_sync(0xffffffffu, adj[(size_t)row * N_NODES + j] != 0);
        if (lane == 0) bits[row * NWORDS + wq] = b;
    }
}

// ---------------- prep: x fp32 -> bf16 A-fragments ----------------
__global__ void prep_afx_kernel(const float* __restrict__ x, uint4* __restrict__ af)
{
    const int c = blockIdx.x;
    const int w = threadIdx.x >> 5, lane = threadIdx.x & 31;
    const int rg = blockIdx.y * 8 + w;
    const int tg = lane & 3, g = lane >> 2;
    const float* p = x + (size_t)(rg * 16 + g) * NFEAT + c * 16 + tg * 2;
    float2 x0 = *(const float2*)p;
    float2 x1 = *(const float2*)(p + 8 * NFEAT);
    float2 x2 = *(const float2*)(p + 8);
    float2 x3 = *(const float2*)(p + 8 * NFEAT + 8);
    uint4 v;
    v.x = pack_bf2(x0.x, x0.y);
    v.y = pack_bf2(x1.x, x1.y);
    v.z = pack_bf2(x2.x, x2.y);
    v.w = pack_bf2(x3.x, x3.y);
    af[((size_t)rg * KC1 + c) * 32 + lane] = v;
}

// ---------------- prep: fp32 [h][chunks*16][cols] -> bf16 B fragments ----------
__global__ void prep_frag_kernel(const float* __restrict__ src, uint2* __restrict__ dst,
                                 int cols)
{
    const int c = blockIdx.x, h = blockIdx.y, tid = threadIdx.x;
    const int t = tid >> 5, l = tid & 31;
    const int tg = l & 3, g = l >> 2;
    const int NT = cols / 8;
    const int nchunk = gridDim.x;
    const float* p = src + (size_t)h * nchunk * 16 * cols
                   + (size_t)(c * 16 + tg * 2) * cols + t * 8 + g;
    uint2 v;
    v.x = pack_bf2(p[0], p[cols]);
    v.y = pack_bf2(p[8 * cols], p[9 * cols]);
    dst[((size_t)(h * nchunk + c) * NT + t) * 32 + l] = v;
}

// ---------------- fragment GEMM (group-staged B), fused dots + B-frag epilogue --
// 256 threads, 8 warps; warp w -> row group rg = blockIdx.x*8 + w.
// Epilogue: acc -> bf16 smem tile -> B-fragments for the NEXT kernel (agg),
// replacing the old bf16-C + separate repack pass (identical rounding).
template<int NT>
__global__ void __launch_bounds__(256, 2)
gemm_frag_kernel(const uint4* __restrict__ afrag, const uint2* __restrict__ bfrag,
                 uint2* __restrict__ bout,
                 const float* __restrict__ v1, const float* __restrict__ v2,
                 float* __restrict__ o1, float* __restrict__ o2)
{
    constexpr int SBN   = GRP * NT * 32;            // uint2 per buffer
    constexpr int LDT   = NT * 8 + 8;               // halves per smem row
    constexpr int SB_B  = 2 * SBN * 8;
    constexpr int TR_B  = 128 * LDT * 2;
    __shared__ __align__(16) char smem[(SB_B > TR_B) ? SB_B : TR_B];
    uint2* sB0 = (uint2*)smem;
    uint2* sB1 = (uint2*)smem + SBN;
    unsigned short* sT = (unsigned short*)smem;

    const int tid = threadIdx.x;
    const int w = tid >> 5, lane = tid & 31;
    const int tg = lane & 3, g = lane >> 2;
    const int h = blockIdx.y;
    const int rg = blockIdx.x * 8 + w;
    const int r0 = rg * 16 + g, r1 = r0 + 8;
    constexpr int G = KC1 / GRP;

    const uint4* af = afrag + (size_t)rg * KC1 * 32 + lane;
    const uint2* bf = bfrag + (size_t)h * KC1 * NT * 32;

    float acc[NT][4];
#pragma unroll
    for (int t = 0; t < NT; t++)
#pragma unroll
        for (int q = 0; q < 4; q++) acc[t][q] = 0.f;

    stage_chunk<GRP * NT * 256>(sB0, bf, tid);
    CP_COMMIT();

    for (int gr = 0; gr < G; gr++) {
        if (gr + 1 < G) {
            stage_chunk<GRP * NT * 256>((gr & 1) ? sB0 : sB1,
                                        bf + (size_t)(gr + 1) * GRP * NT * 32, tid);
            CP_COMMIT();
            CP_WAIT(1);
        } else {
            CP_WAIT(0);
        }
        __syncthreads();
        const uint2* sbase = (gr & 1) ? sB1 : sB0;
#pragma unroll
        for (int cc = 0; cc < GRP; cc++) {
            uint4 a = af[(size_t)(gr * GRP + cc) * 32];
            const uint2* bp = sbase + cc * NT * 32 + lane;
#pragma unroll
            for (int t = 0; t < NT; t++) {
                uint2 b = bp[t * 32];
                MMA_BF16(acc[t], a.x, a.y, a.z, a.w, b.x, b.y);
            }
        }
        __syncthreads();
    }

    // fused dots with v1, v2
    {
        const float* w1 = v1 + h * (NT * 8);
        const float* w2 = v2 + h * (NT * 8);
        float s10 = 0.f, s11 = 0.f, s20 = 0.f, s21 = 0.f;
#pragma unroll
        for (int t = 0; t < NT; t++) {
            const int d = t * 8 + tg * 2;
            float u0 = w1[d], u1 = w1[d + 1];
            float q0 = w2[d], q1 = w2[d + 1];
            s10 += acc[t][0] * u0 + acc[t][1] * u1;
            s11 += acc[t][2] * u0 + acc[t][3] * u1;
            s20 += acc[t][0] * q0 + acc[t][1] * q1;
            s21 += acc[t][2] * q0 + acc[t][3] * q1;
        }
#pragma unroll
        for (int o = 1; o <= 2; o <<= 1) {
            s10 += __shfl_xor_sync(0xffffffffu, s10, o);
            s11 += __shfl_xor_sync(0xffffffffu, s11, o);
            s20 += __shfl_xor_sync(0xffffffffu, s20, o);
            s21 += __shfl_xor_sync(0xffffffffu, s21, o);
        }
        if (tg == 0) {
            o1[h * N_NODES + r0] = s10;
            o1[h * N_NODES + r1] = s11;
            o2[h * N_NODES + r0] = s20;
            o2[h * N_NODES + r1] = s21;
        }
    }

    // epilogue: bf16 transpose tile -> B fragments (chunk space: blockIdx.x*8 + 0..7)
    {
        const int rl0 = w * 16 + g, rl1 = rl0 + 8;    // local rows
#pragma unroll
        for (int t = 0; t < NT; t++) {
            const int d = t * 8 + tg * 2;
            *(u32*)&sT[rl0 * LDT + d] = pack_bf2(acc[t][0], acc[t][1]);
            *(u32*)&sT[rl1 * LDT + d] = pack_bf2(acc[t][2], acc[t][3]);
        }
        __syncthreads();
        const int cl = tid >> 5, l2 = tid & 31;
        const int tg2 = l2 & 3, g2 = l2 >> 2;
        const int j0 = cl * 16 + tg2 * 2;
        uint2* bd = bout + (size_t)h * AC * NT * 32
                  + (size_t)(blockIdx.x * 8 + cl) * NT * 32 + l2;
#pragma unroll
        for (int t = 0; t < NT; t++) {
            const int d = t * 8 + g2;
            uint2 v;
            v.x = (u32)sT[j0 * LDT + d]       | ((u32)sT[(j0 + 1) * LDT + d] << 16);
            v.y = (u32)sT[(j0 + 8) * LDT + d] | ((u32)sT[(j0 + 9) * LDT + d] << 16);
            bd[t * 32] = v;
        }
    }
}

// ---------------- per-head unmasked max of f2 ----------------
__global__ void headmax_kernel(const float* __restrict__ v, float* __restrict__ c)
{
    __shared__ float red[256];
    const int h = blockIdx.x, tid = threadIdx.x;
    float mx = -INFINITY;
    for (int j = tid; j < N_NODES; j += 256) mx = fmaxf(mx, v[h * N_NODES + j]);
    red[tid] = mx;
    __syncthreads();
    for (int s = 128; s > 0; s >>= 1) {
        if (tid < s) red[tid] = fmaxf(red[tid], red[tid + s]);
        __syncthreads();
    }
    if (tid == 0) c[h] = red[0];
}

// ---------------- factorized exp tables (M_i = lrelu(f1_i + c_h) inline) -------
__global__ void fill_e_kernel(const float* __restrict__ f1, const float* __restrict__ f2,
                              const float* __restrict__ c,
                              float2* __restrict__ e1, float2* __restrict__ e2)
{
    const int idx = blockIdx.x * 256 + threadIdx.x;
    const int h = idx >> 12;
    const float ch = c[h];
    const float s = f1[idx] + ch;
    const float M = fmaxf(s, ALPHA * s);          // >= masked row max, softmax-safe
    const float t = f2[idx] - ch;
    e1[idx] = make_float2(__expf(s - M), __expf(ALPHA * s - M));
    e2[idx] = make_float2(__expf(t), __expf(ALPHA * t));
}

// ---------------- attention apply (group-staged B, factorized P) ----------------
// 256 threads, 8 warps; warp w -> row group rg = blockIdx.x*8 + w.
template<int NT, bool AFRAG>
__global__ void __launch_bounds__(256, 2)
agg_kernel(const u32* __restrict__ bits, const float2* __restrict__ e1,
           const float2* __restrict__ e2, const uint2* __restrict__ bfrag,
           void* __restrict__ outp)
{
    constexpr int SBN = GRP * NT * 32;
    __shared__ __align__(16) uint2 sB[2][SBN];
    const int tid = threadIdx.x;
    const int w = tid >> 5, lane = tid & 31;
    const int tg = lane & 3, g = lane >> 2;
    const int h = blockIdx.y;
    const int hN = h * N_NODES;
    const int rg = blockIdx.x * 8 + w;
    const int r0 = rg * 16 + g, r1 = r0 + 8;
    constexpr int G = AC / GRP;                   // 64 groups of 4 chunks

    const float2 E1a = e1[hN + r0], E1b = e1[hN + r1];
    const float2* e2h = e2 + hN;
    const u32* rowA = bits + (size_t)r0 * NWORDS;
    const u32* rowB = bits + (size_t)r1 * NWORDS;
    const uint2* bf = bfrag + (size_t)h * AC * NT * 32;

    float acc[NT][4];
#pragma unroll
    for (int t = 0; t < NT; t++)
#pragma unroll
        for (int q = 0; q < 4; q++) acc[t][q] = 0.f;

    float z0 = 0.f, z1 = 0.f;

    stage_chunk<GRP * NT * 256>(sB[0], bf, tid);
    CP_COMMIT();

    for (int gr = 0; gr < G; gr++) {
        if (gr + 1 < G) {
            stage_chunk<GRP * NT * 256>(sB[(gr + 1) & 1],
                                        bf + (size_t)(gr + 1) * GRP * NT * 32, tid);
            CP_COMMIT();
            CP_WAIT(1);
        } else {
            CP_WAIT(0);
        }
        __syncthreads();

        u32 wrdA[2] = { rowA[2 * gr], rowA[2 * gr + 1] };
        u32 wrdB[2] = { rowB[2 * gr], rowB[2 * gr + 1] };
        const uint2* sbase = sB[gr & 1] + lane;

#pragma unroll
        for (int cc = 0; cc < GRP; cc++) {
            const int c = gr * GRP + cc;
            const u32 wA = wrdA[cc >> 1];
            const u32 wB = wrdB[cc >> 1];
            const int sh = (cc & 1) * 16 + tg * 2;
            const int jA = c * 16 + tg * 2;
            const int jB = jA + 8;
            float4 eA = *(const float4*)(e2h + jA);
            float4 eB = *(const float4*)(e2h + jB);

            float p00 = ((wA >> sh)       & 1u) ? fmaxf(E1a.x * eA.x, E1a.y * eA.y) : 0.f;
            float p01 = ((wA >> (sh + 1)) & 1u) ? fmaxf(E1a.x * eA.z, E1a.y * eA.w) : 0.f;
            float p02 = ((wA >> (sh + 8)) & 1u) ? fmaxf(E1a.x * eB.x, E1a.y * eB.y) : 0.f;
            float p03 = ((wA >> (sh + 9)) & 1u) ? fmaxf(E1a.x * eB.z, E1a.y * eB.w) : 0.f;
            float p10 = ((wB >> sh)       & 1u) ? fmaxf(E1b.x * eA.x, E1b.y * eA.y) : 0.f;
            float p11 = ((wB >> (sh + 1)) & 1u) ? fmaxf(E1b.x * eA.z, E1b.y * eA.w) : 0.f;
            float p12 = ((wB >> (sh + 8)) & 1u) ? fmaxf(E1b.x * eB.x, E1b.y * eB.y) : 0.f;
            float p13 = ((wB >> (sh + 9)) & 1u) ? fmaxf(E1b.x * eB.z, E1b.y * eB.w) : 0.f;

            z0 += (p00 + p01) + (p02 + p03);
            z1 += (p10 + p11) + (p12 + p13);

            u32 a0 = pack_bf2(p00, p01);
            u32 a1 = pack_bf2(p10, p11);
            u32 a2 = pack_bf2(p02, p03);
            u32 a3 = pack_bf2(p12, p13);

            const uint2* bp = sbase + cc * NT * 32;
#pragma unroll
            for (int t = 0; t < NT; t++) {
                uint2 b = bp[t * 32];
                MMA_BF16(acc[t], a0, a1, a2, a3, b.x, b.y);
            }
        }
        __syncthreads();
    }

    z0 += __shfl_xor_sync(0xffffffffu, z0, 1);
    z0 += __shfl_xor_sync(0xffffffffu, z0, 2);
    z1 += __shfl_xor_sync(0xffffffffu, z1, 1);
    z1 += __shfl_xor_sync(0xffffffffu, z1, 2);
    const float iz0 = 1.f / z0;
    const float iz1 = 1.f / z1;

    if (AFRAG) {
        // write elu(out/Z) as A-fragments of the concatenated feature matrix
        uint4* af = (uint4*)outp;
#pragma unroll
        for (int ct = 0; ct < NT / 2; ct++) {
            const int t0 = 2 * ct, t1 = 2 * ct + 1;
            uint4 v;
            v.x = pack_bf2(elu_f(acc[t0][0] * iz0), elu_f(acc[t0][1] * iz0));
            v.y = pack_bf2(elu_f(acc[t0][2] * iz1), elu_f(acc[t0][3] * iz1));
            v.z = pack_bf2(elu_f(acc[t1][0] * iz0), elu_f(acc[t1][1] * iz0));
            v.w = pack_bf2(elu_f(acc[t1][2] * iz1), elu_f(acc[t1][3] * iz1));
            af[((size_t)rg * KC1 + h * (NT / 2) + ct) * 32 + lane] = v;
        }
    } else {
        float* out = (float*)outp;
        float* row0 = out + (size_t)r0 * (NT * 8) + tg * 2;
        float* row1 = out + (size_t)r1 * (NT * 8) + tg * 2;
#pragma unroll
        for (int t = 0; t < NT; t++) {
            *(float2*)(row0 + t * 8) = make_float2(elu_f(acc[t][0] * iz0),
                                                   elu_f(acc[t][1] * iz0));
            *(float2*)(row1 + t * 8) = make_float2(elu_f(acc[t][2] * iz1),
                                                   elu_f(acc[t][3] * iz1));
        }
    }
}

// ---------------- final log_softmax over 64 classes ----------------
__global__ void lsm_kernel(const float* __restrict__ in, float* __restrict__ out)
{
    int warp = (blockIdx.x * blockDim.x + threadIdx.x) >> 5;
    int lane = threadIdx.x & 31;
    if (warp >= N_NODES) return;
    const float* row = in + (long)warp * NCLASS;
    float v0 = row[lane];
    float v1 = row[lane + 32];
    float m = fmaxf(v0, v1);
#pragma unroll
    for (int o = 16; o > 0; o >>= 1) m = fmaxf(m, __shfl_xor_sync(0xffffffffu, m, o));
    float s = expf(v0 - m) + expf(v1 - m);
#pragma unroll
    for (int o = 16; o > 0; o >>= 1) s += __shfl_xor_sync(0xffffffffu, s, o);
    float ls = m + logf(s);
    out[(long)warp * NCLASS + lane]      = v0 - ls;
    out[(long)warp * NCLASS + lane + 32] = v1 - ls;
}

// ---------------- launch ----------------
extern "C" void kernel_launch(void* const* d_in, const int* in_sizes, int n_in,
                              void* d_out, int out_size)
{
    const float* x   = (const float*)d_in[0];
    const int*   adj = (const int*)  d_in[1];
    const float* W   = (const float*)d_in[2];
    const float* a1  = (const float*)d_in[3];
    const float* a2  = (const float*)d_in[4];
    const float* Wo  = (const float*)d_in[5];
    const float* ao1 = (const float*)d_in[6];
    const float* ao2 = (const float*)d_in[7];
    float* out = (float*)d_out;

    u32* bits;
    uint4 *afx, *afh;
    uint2 *wfrag, *wofrag, *whf, *whof;
    float *f1, *f2, *c1, *g1, *g2, *c2, *obuf;
    float2 *e1, *e2, *e1o, *e2o;
    cudaGetSymbolAddress((void**)&bits,   g_bits);
    cudaGetSymbolAddress((void**)&afx,    g_afx);
    cudaGetSymbolAddress((void**)&wfrag,  g_wfrag);
    cudaGetSymbolAddress((void**)&f1,     g_f1);
    cudaGetSymbolAddress((void**)&f2,     g_f2);
    cudaGetSymbolAddress((void**)&c1,     g_c1);
    cudaGetSymbolAddress((void**)&e1,     g_e1);
    cudaGetSymbolAddress((void**)&e2,     g_e2);
    cudaGetSymbolAddress((void**)&whf,    g_whf);
    cudaGetSymbolAddress((void**)&afh,    g_afh);
    cudaGetSymbolAddress((void**)&wofrag, g_wofrag);
    cudaGetSymbolAddress((void**)&g1,     g_g1);
    cudaGetSymbolAddress((void**)&g2,     g_g2);
    cudaGetSymbolAddress((void**)&c2,     g_c2);
    cudaGetSymbolAddress((void**)&e1o,    g_e1o);
    cudaGetSymbolAddress((void**)&e2o,    g_e2o);
    cudaGetSymbolAddress((void**)&whof,   g_whof);
    cudaGetSymbolAddress((void**)&obuf,   g_obuf);

    // preprocessing
    pack_adj_kernel<<<N_NODES, 256>>>(adj, bits);
    prep_afx_kernel<<<dim3(KC1, NRG / 8), 256>>>(x, afx);
    prep_frag_kernel<<<dim3(KC1, NHEADS), 512>>>(W, wfrag, NHID);

    // ---- layer 1 ----
    gemm_frag_kernel<16><<<dim3(NRG / 8, NHEADS), 256>>>(
        afx, wfrag, whf, a1, a2, f1, f2);
    headmax_kernel<<<NHEADS, 256>>>(f2, c1);
    fill_e_kernel<<<(NHEADS * N_NODES) / 256, 256>>>(f1, f2, c1, e1, e2);
    agg_kernel<16, true><<<dim3(NRG / 8, NHEADS), 256>>>(bits, e1, e2, whf, afh);

    // ---- layer 2 ----
    prep_frag_kernel<<<dim3(KC1, 1), 256>>>(Wo, wofrag, NCLASS);
    gemm_frag_kernel<8><<<dim3(NRG / 8, 1), 256>>>(
        afh, wofrag, whof, ao1, ao2, g1, g2);
    headmax_kernel<<<1, 256>>>(g2, c2);
    fill_e_kernel<<<N_NODES / 256, 256>>>(g1, g2, c2, e1o, e2o);
    agg_kernel<8, false><<<dim3(NRG / 8, 1), 256>>>(bits, e1o, e2o, whof, obuf);

    lsm_kernel<<<N_NODES / 8, 256>>>(obuf, out);
}